// round 15
// baseline (speedup 1.0000x reference)
#include <cuda_runtime.h>
#include <cuda_bf16.h>
#include <cuda_fp16.h>
#include <math.h>
#include <stdint.h>

#define NB 2
#define NL 1024
#define NH 8
#define ND 64
#define NDM 768
#define HD 512        /* NH*ND */
#define KAUG_X 1536   /* 2*768: [x_hi | x_lo] vs [w_hi | w_hi] */
#define KAUG_O 1024   /* 2*512 */

// ------------------------- device scratch (no allocation) --------------------
static __device__ __align__(16) __half g_Aaug [NB*NL*KAUG_X];   // x hi|lo (fp16)
static __device__ __align__(16) __half g_Waug [2048*KAUG_X];    // Wq|Wk|Wv|W2 hi|hi
static __device__ __align__(16) __half g_AOaug[NB*NL*KAUG_O];   // attn out hi|lo
static __device__ __align__(16) __half g_WOaug[NDM*KAUG_O];     // Wo hi|hi
static __device__ __align__(16) float g_W2 [HD*NDM];            // folded Wq^T@wpos
static __device__ __align__(16) float g_wu [NH*NDM];            // folded Wk^T@u_bias
// fp16 attention operands, [b][h][tok][d] (Q,K) and [b][h][d][tok] (V^T)
static __device__ __align__(16) __half g_qh[NB*NH*NL*ND];
static __device__ __align__(16) __half g_ql[NB*NH*NL*ND];
static __device__ __align__(16) __half g_kh[NB*NH*NL*ND];
static __device__ __align__(16) __half g_vth[NB*NH*ND*NL];
static __device__ __align__(16) __half g_vtl[NB*NH*ND*NL];
static __device__ __align__(16) float g_uk [NB*NH*NL];
static __device__ __align__(16) float g_Su [NB*NH*NL*33];
static __device__ __align__(16) float g_Ss [NB*NH*NL*33];
static __device__ __align__(16) float g_VrU[NH*33];
static __device__ __align__(16) float g_VrS[NH*33];
static __device__ int   g_t[NL];

// ------------------------- helpers -------------------------------------------
__device__ __forceinline__ void split_hl16(float v, __half& h, __half& l) {
    h = __float2half(v);
    l = __float2half(v - __half2float(h));
}

// -------- merged pre-kernel: fold_w2 | fold_wu | prep | conv_x | conv_wo -----
// blocks [0,512): W2; [512,520): wu; [520,532): prep; [532,2580): conv_x;
// [2580,3348): conv_wo
__global__ void pre_kernel(const float* __restrict__ Wq,
                           const float* __restrict__ Wk,
                           const float* __restrict__ u_bias,
                           const float* __restrict__ w_pos,
                           const float* __restrict__ v_bias,
                           const float* __restrict__ x,
                           const float* __restrict__ Wo)
{
    const int tid = threadIdx.x;
    const int blk = blockIdx.x;

    if (blk < 512) {                       // ---- fold_w2 ----
        __shared__ float wp[64];
        int hn = blk, h = hn >> 6, n = hn & 63;
        if (tid < 64) wp[tid] = w_pos[h*4096 + tid*64 + n];
        __syncthreads();
        for (int m = tid; m < NDM; m += 256) {
            float s = 0.f;
#pragma unroll 16
            for (int d = 0; d < 64; d++)
                s += Wq[(size_t)(h*64 + d)*NDM + m] * wp[d];
            g_W2[(size_t)hn*NDM + m] = s;
        }
        return;
    }
    if (blk < 520) {                       // ---- fold_wu: wu[h] = Wk_h^T u_h ----
        __shared__ float us[64];
        int h = blk - 512;
        if (tid < 64) us[tid] = u_bias[h*64 + tid];
        __syncthreads();
        for (int m = tid; m < NDM; m += 256) {
            float s = 0.f;
#pragma unroll 16
            for (int d = 0; d < 64; d++)
                s += Wk[(size_t)(h*64 + d)*NDM + m] * us[d];
            g_wu[(size_t)h*NDM + m] = s;
        }
        return;
    }
    if (blk < 532) {                       // ---- prep ----
        int sub = blk - 520;
        if (sub < 4) {
            __shared__ float cw[32];
            if (tid < 32) {
                float pr = expf(logf((float)(NL+1) * 0.5f) / 32.f);
                cw[tid] = powf(pr, (float)(tid+1));
            }
            __syncthreads();
            int a = sub*256 + tid;
            int t = 32;
            for (int f = 0; f < 32; f++)
                if ((float)a <= cw[f]) { t = f; break; }
            g_t[a] = t;
            return;
        }
        int hh = sub - 4;
        __shared__ float vws[64];
        if (tid < 64) {
            int n = tid;
            float s = 0.f;
            for (int d = 0; d < 64; d++)
                s += v_bias[hh*64 + d] * w_pos[hh*4096 + d*64 + n];
            vws[n] = s;
        }
        __syncthreads();
        if (tid < 2) {
            int half = tid;
            float* dst = (half ? g_VrS : g_VrU) + hh*33;
            const float* src = vws + half*32;
            float run = 0.f;
            dst[32] = 0.f;
            for (int f = 31; f >= 0; f--) { run += src[f]; dst[f] = run; }
        }
        return;
    }
    if (blk < 2580) {                      // ---- conv_x ----
        int row = blk - 532;
        const float* src = x + (size_t)row * NDM;
        __half* dst = g_Aaug + (size_t)row * KAUG_X;
        for (int c = tid; c < NDM; c += 256) {
            __half h, l; split_hl16(src[c], h, l);
            dst[c] = h; dst[NDM + c] = l;
        }
        return;
    }
    {                                      // ---- conv_wo ----
        int r = blk - 2580;
        const float* src = Wo + (size_t)r * HD;
        __half* dst = g_WOaug + (size_t)r * KAUG_O;
        for (int c = tid; c < HD; c += 256) {
            __half h = __float2half(src[c]);
            dst[c] = h; dst[HD + c] = h;
        }
    }
}

// -------- conv_w (blocks 0..2047) + uk = x @ wu^T (blocks 2048..2303) --------
__global__ void convw_uk_kernel(const float* __restrict__ Wq,
                                const float* __restrict__ Wk,
                                const float* __restrict__ Wv,
                                const float* __restrict__ x) {
    int blk = blockIdx.x;
    if (blk < 2048) {
        int r = blk;
        const float* src;
        if (r < 512)        src = Wq + (size_t)r * NDM;
        else if (r < 1024)  src = Wk + (size_t)(r-512) * NDM;
        else if (r < 1536)  src = Wv + (size_t)(r-1024) * NDM;
        else                src = g_W2 + (size_t)(r-1536) * NDM;
        __half* dst = g_Waug + (size_t)r * KAUG_X;
        for (int c = threadIdx.x; c < NDM; c += 256) {
            __half h = __float2half(src[c]);
            dst[c] = h; dst[NDM + c] = h;
        }
        return;
    }
    // uk: warp per (b,j) row; 256 blocks * 8 warps = 2048 rows
    int wrow = (blk - 2048)*8 + (threadIdx.x >> 5);   // b*1024 + j
    int lane = threadIdx.x & 31;
    const float* xr = x + (size_t)wrow * NDM;
    float acc[NH];
#pragma unroll
    for (int h = 0; h < NH; h++) acc[h] = 0.f;
    for (int m = lane; m < NDM; m += 32) {
        float xv = xr[m];
#pragma unroll
        for (int h = 0; h < NH; h++)
            acc[h] += xv * g_wu[(size_t)h*NDM + m];
    }
#pragma unroll
    for (int h = 0; h < NH; h++) {
#pragma unroll
        for (int o = 16; o >= 1; o >>= 1)
            acc[h] += __shfl_xor_sync(0xffffffffu, acc[h], o);
    }
    int b = wrow >> 10, j = wrow & 1023;
    if (lane < NH)
        g_uk[(size_t)(b*NH + lane)*NL + j] = acc[lane];
}

// ------------------------- mma.sync fp16 GEMM: C = A @ Bw^T ------------------
#define BM 128
#define BN 128
#define BK 32
#define GSTR 40
#define SMEM_AB ((2*BM*GSTR + 2*BN*GSTR)*2)   /* 40960 bytes */

__device__ __forceinline__ void mma16816h(float* c, const uint32_t* a, const uint32_t* b) {
    asm volatile(
        "mma.sync.aligned.m16n8k16.row.col.f32.f16.f16.f32 "
        "{%0,%1,%2,%3}, {%4,%5,%6,%7}, {%8,%9}, {%0,%1,%2,%3};"
        : "+f"(c[0]), "+f"(c[1]), "+f"(c[2]), "+f"(c[3])
        : "r"(a[0]), "r"(a[1]), "r"(a[2]), "r"(a[3]), "r"(b[0]), "r"(b[1]));
}

__global__ __launch_bounds__(256, 1)
void gemm_mma(int which, const float* __restrict__ bias, float* __restrict__ Cout)
{
    __shared__ __align__(16) char smraw[SMEM_AB];
    __half* sAb = (__half*)smraw;                                   // [2][BM*GSTR]
    __half* sBb = (__half*)(smraw + 2*BM*GSTR*2);                   // [2][BN*GSTR]

    const int tid = threadIdx.x;
    const int wid = tid >> 5, lane = tid & 31;
    const int wm = wid >> 2, wn = wid & 3;
    const int m0 = blockIdx.y * BM, n0 = blockIdx.x * BN;

    const __half *A, *Bw;
    int Kaug, Ntot;
    if (which == 0) { A = g_Aaug;  Bw = g_Waug;  Kaug = KAUG_X; Ntot = 0; }
    else            { A = g_AOaug; Bw = g_WOaug; Kaug = KAUG_O; Ntot = NDM; }
    const int nk = Kaug / BK;

    const int ldrow = tid >> 2, ldg = tid & 3;

    auto prefetch = [&](int c) {
        int p = c & 1;
        {
            const __half* Ab = A + (size_t)(m0 + ldrow) * Kaug + c*BK + ldg*8;
#pragma unroll
            for (int s = 0; s < 2; s++) {
                uint32_t dst = (uint32_t)__cvta_generic_to_shared(
                    sAb + p*BM*GSTR + (ldrow + s*64)*GSTR + ldg*8);
                const void* src = Ab + (size_t)(s*64) * Kaug;
                asm volatile("cp.async.cg.shared.global [%0], [%1], 16;" :: "r"(dst), "l"(src));
            }
        }
        {
            const __half* Bb = Bw + (size_t)(n0 + ldrow) * Kaug + c*BK + ldg*8;
#pragma unroll
            for (int s = 0; s < 2; s++) {
                uint32_t dst = (uint32_t)__cvta_generic_to_shared(
                    sBb + p*BN*GSTR + (ldrow + s*64)*GSTR + ldg*8);
                const void* src = Bb + (size_t)(s*64) * Kaug;
                asm volatile("cp.async.cg.shared.global [%0], [%1], 16;" :: "r"(dst), "l"(src));
            }
        }
        asm volatile("cp.async.commit_group;" ::: "memory");
    };

    float acc[4][4][4];
#pragma unroll
    for (int i = 0; i < 4; i++)
#pragma unroll
        for (int j = 0; j < 4; j++)
#pragma unroll
            for (int r = 0; r < 4; r++) acc[i][j][r] = 0.f;

    prefetch(0);

    for (int c = 0; c < nk; c++) {
        int p = c & 1;
        if (c + 1 < nk) {
            prefetch(c + 1);
            asm volatile("cp.async.wait_group 1;" ::: "memory");
        } else {
            asm volatile("cp.async.wait_group 0;" ::: "memory");
        }
        __syncthreads();

        uint32_t aB = (uint32_t)__cvta_generic_to_shared(sAb + p*BM*GSTR);
        uint32_t bB = (uint32_t)__cvta_generic_to_shared(sBb + p*BN*GSTR);

#pragma unroll
        for (int ks = 0; ks < 2; ks++) {
            uint32_t a[4][4];
#pragma unroll
            for (int i = 0; i < 4; i++) {
                uint32_t addr = aB + (uint32_t)(
                    ((wm*64 + i*16 + (lane & 15))*GSTR + ((lane >> 4)*8) + ks*16) * 2);
                asm volatile("ldmatrix.sync.aligned.m8n8.x4.shared.b16 {%0,%1,%2,%3}, [%4];"
                    : "=r"(a[i][0]), "=r"(a[i][1]), "=r"(a[i][2]), "=r"(a[i][3]) : "r"(addr));
            }
            uint32_t b[4][2];
#pragma unroll
            for (int jp = 0; jp < 2; jp++) {
                uint32_t addr = bB + (uint32_t)(
                    ((wn*32 + jp*16 + (lane & 7) + ((lane >> 4) << 3))*GSTR
                     + (((lane >> 3) & 1) << 3) + ks*16) * 2);
                asm volatile("ldmatrix.sync.aligned.m8n8.x4.shared.b16 {%0,%1,%2,%3}, [%4];"
                    : "=r"(b[2*jp][0]), "=r"(b[2*jp][1]),
                      "=r"(b[2*jp+1][0]), "=r"(b[2*jp+1][1]) : "r"(addr));
            }
#pragma unroll
            for (int i = 0; i < 4; i++)
#pragma unroll
                for (int j = 0; j < 4; j++)
                    mma16816h(acc[i][j], a[i], b[j]);
        }
        __syncthreads();
    }

    // ----------------- epilogues -----------------
    if (which == 1) {
#pragma unroll
        for (int i = 0; i < 4; i++) {
            int r0 = m0 + wm*64 + i*16 + (lane >> 2);
#pragma unroll
            for (int j = 0; j < 4; j++) {
                int col = n0 + wn*32 + j*8 + (lane & 3)*2;
                float b0 = bias[col], b1 = bias[col+1];
                *(float2*)(Cout + (size_t)r0 * Ntot + col) =
                    make_float2(acc[i][j][0] + b0, acc[i][j][1] + b1);
                *(float2*)(Cout + (size_t)(r0 + 8) * Ntot + col) =
                    make_float2(acc[i][j][2] + b0, acc[i][j][3] + b1);
            }
        }
        return;
    }

    if (n0 >= 1536) {
        // QW region: suffix sums (+vr) computed in-block, straight to g_Su/g_Ss.
        // Stage 64 rows x 128 cols (stride 132) into the smem buffer per pass.
        float* scr = (float*)smraw;   // 64*132*4 = 33792 <= 40960
        int hbase = (n0 - 1536) >> 6;
#pragma unroll
        for (int pass = 0; pass < 2; pass++) {
            if (wm == pass) {
#pragma unroll
                for (int i = 0; i < 4; i++) {
                    int rl = i*16 + (lane >> 2);
#pragma unroll
                    for (int j = 0; j < 4; j++) {
                        int cl = wn*32 + j*8 + (lane & 3)*2;
                        scr[rl*132 + cl]       = acc[i][j][0];
                        scr[rl*132 + cl + 1]   = acc[i][j][1];
                        scr[(rl+8)*132 + cl]     = acc[i][j][2];
                        scr[(rl+8)*132 + cl + 1] = acc[i][j][3];
                    }
                }
            }
            __syncthreads();
            {
                int rl = tid >> 2, head = (tid >> 1) & 1, hf = tid & 1;
                int grow = m0 + pass*64 + rl;
                int b = grow >> 10, tok = grow & 1023;
                int h = hbase + head;
                const float* vr = (hf ? g_VrS : g_VrU) + h*33;
                float* dst = (hf ? g_Ss : g_Su) + (size_t)((b*NH + h)*NL + tok)*33;
                const float* src = scr + rl*132 + head*64 + hf*32;
                float run = 0.f;
                dst[32] = vr[32];
#pragma unroll
                for (int f = 31; f >= 0; f--) { run += src[f]; dst[f] = run + vr[f]; }
            }
            __syncthreads();
        }
        return;
    }

    // Q|K|V regions: scatter fp16 attention operands
    auto emit = [&](int row, int col, float v0, float v1) {
        int reg = col >> 9;
        int bb = row >> 10, tok = row & 1023;
        int h = (col >> 6) & 7, d = col & 63;
        __half h0, l0, h1, l1;
        split_hl16(v0, h0, l0); split_hl16(v1, h1, l1);
        if (reg == 2) {
            size_t vk = ((size_t)((bb*8+h)*64 + d))*1024 + tok;
            g_vth[vk] = h0; g_vtl[vk] = l0;
            g_vth[vk + 1024] = h1; g_vtl[vk + 1024] = l1;
            return;
        }
        size_t qk = ((size_t)((bb*8+h)*1024 + tok))*64 + d;
        if (reg == 0) {
            *(__half2*)(g_qh + qk) = __half2(h0, h1);
            *(__half2*)(g_ql + qk) = __half2(l0, l1);
        } else {
            *(__half2*)(g_kh + qk) = __half2(h0, h1);
        }
    };
#pragma unroll
    for (int i = 0; i < 4; i++) {
        int r0 = m0 + wm*64 + i*16 + (lane >> 2);
#pragma unroll
        for (int j = 0; j < 4; j++) {
            int col = n0 + wn*32 + j*8 + (lane & 3)*2;
            emit(r0,     col, acc[i][j][0], acc[i][j][1]);
            emit(r0 + 8, col, acc[i][j][2], acc[i][j][3]);
        }
    }
}

// ---------------- flash attention, fp16 HMMA, factored rel-pos bias ----------
#define QSTR 72    /* Q/K smem row stride (fp16): 144B, 144%128=16 -> conflict-free */
#define VSTR 136   /* V^T smem row stride: 272B, %128=16 */
#define AOFF_QH 0
#define AOFF_QL (AOFF_QH + 128*QSTR*2)
#define AOFF_KH (AOFF_QL + 128*QSTR*2)
#define AOFF_VH (AOFF_KH + 128*QSTR*2)
#define AOFF_VL (AOFF_VH + 64*VSTR*2)
#define AOFF_SU (AOFF_VL + 64*VSTR*2)
#define AOFF_SS (AOFF_SU + 128*33*4)
#define AOFF_UK (AOFF_SS + 128*33*4)
#define AOFF_TS (AOFF_UK + 1024*4)
#define ATTN_SMEM (AOFF_TS + 1024*4)

__global__ __launch_bounds__(256, 1)
void attn_kernel()
{
    extern __shared__ char smc[];
    __half* sQh = (__half*)(smc + AOFF_QH);
    __half* sQl = (__half*)(smc + AOFF_QL);
    __half* sKh = (__half*)(smc + AOFF_KH);
    __half* sVh = (__half*)(smc + AOFF_VH);
    __half* sVl = (__half*)(smc + AOFF_VL);
    float* SuS = (float*)(smc + AOFF_SU);
    float* SsS = (float*)(smc + AOFF_SS);
    float* uks = (float*)(smc + AOFF_UK);
    int*   ts  = (int*)(smc + AOFF_TS);

    const int tid = threadIdx.x;
    const int wid = tid >> 5, lane = tid & 31;
    const int it = blockIdx.x, hh = blockIdx.y, b = blockIdx.z;
    const int i0 = it * 128;
    const int bh = b*NH + hh;
    const float scale = 0.125f;

    const size_t qkbase = (size_t)(bh*NL) * ND;      // Q/K [tok][d]
    const size_t vtbase = (size_t)(bh*ND) * NL;      // V^T [d][tok]

    // prologue: Q tiles + tables
    for (int idx = tid; idx < 1024; idx += 256) {    // 128 rows x 8 chunks(16B)
        int row = idx >> 3, g = idx & 7;
        size_t src = qkbase + (size_t)(i0 + row)*ND + g*8;
        *(uint4*)(sQh + row*QSTR + g*8) = *(const uint4*)(g_qh + src);
        *(uint4*)(sQl + row*QSTR + g*8) = *(const uint4*)(g_ql + src);
    }
    for (int idx = tid; idx < 128*33; idx += 256) {
        SuS[idx] = g_Su[(size_t)(bh*NL + i0)*33 + idx];
        SsS[idx] = g_Ss[(size_t)(bh*NL + i0)*33 + idx];
    }
    for (int idx = tid; idx < NL; idx += 256) {
        uks[idx] = g_uk[bh*NL + idx];
        ts[idx]  = g_t[idx];
    }

    const int il0 = wid*16 + (lane >> 2);
    const int ig0 = i0 + il0, ig1 = ig0 + 8;

    float m0_ = -1e30f, m1_ = -1e30f, l0_ = 0.f, l1_ = 0.f;
    float oacc[8][4];
#pragma unroll
    for (int d = 0; d < 8; d++)
#pragma unroll
        for (int e = 0; e < 4; e++) oacc[d][e] = 0.f;

    for (int jc = 0; jc < 8; jc++) {
        const int j0 = jc * 128;
        __syncthreads();
        for (int idx = tid; idx < 1024; idx += 256) {
            int row = idx >> 3, g = idx & 7;
            size_t src = qkbase + (size_t)(j0 + row)*ND + g*8;
            *(uint4*)(sKh + row*QSTR + g*8) = *(const uint4*)(g_kh + src);
        }
        for (int idx = tid; idx < 1024; idx += 256) { // 64 d-rows x 16 chunks
            int d = idx >> 4, g = idx & 15;
            size_t src = vtbase + (size_t)d*NL + j0 + g*8;
            *(uint4*)(sVh + d*VSTR + g*8) = *(const uint4*)(g_vth + src);
            *(uint4*)(sVl + d*VSTR + g*8) = *(const uint4*)(g_vtl + src);
        }
        __syncthreads();

        // ---- S = (Qh + Ql) @ Kh^T  (exact Q, fp16-rounded K) ----
        float sacc[16][4];
#pragma unroll
        for (int jt = 0; jt < 16; jt++)
#pragma unroll
            for (int e = 0; e < 4; e++) sacc[jt][e] = 0.f;

        uint32_t aQbase = (uint32_t)__cvta_generic_to_shared(sQh);
        uint32_t aQlb   = (uint32_t)__cvta_generic_to_shared(sQl);
        uint32_t aKbase = (uint32_t)__cvta_generic_to_shared(sKh);

#pragma unroll
        for (int ks = 0; ks < 4; ks++) {
            uint32_t aqh[4], aql[4];
            {
                uint32_t addr = aQbase + (uint32_t)(
                    ((wid*16 + (lane & 15))*QSTR + (lane >> 4)*8 + ks*16) * 2);
                asm volatile("ldmatrix.sync.aligned.m8n8.x4.shared.b16 {%0,%1,%2,%3}, [%4];"
                    : "=r"(aqh[0]), "=r"(aqh[1]), "=r"(aqh[2]), "=r"(aqh[3]) : "r"(addr));
                addr = aQlb + (uint32_t)(
                    ((wid*16 + (lane & 15))*QSTR + (lane >> 4)*8 + ks*16) * 2);
                asm volatile("ldmatrix.sync.aligned.m8n8.x4.shared.b16 {%0,%1,%2,%3}, [%4];"
                    : "=r"(aql[0]), "=r"(aql[1]), "=r"(aql[2]), "=r"(aql[3]) : "r"(addr));
            }
            uint32_t bk[16][2];
#pragma unroll
            for (int jt2 = 0; jt2 < 8; jt2++) {
                uint32_t addr = aKbase + (uint32_t)(
                    ((jt2*16 + (lane & 7) + ((lane >> 4) << 3))*QSTR
                     + (((lane >> 3) & 1) << 3) + ks*16) * 2);
                asm volatile("ldmatrix.sync.aligned.m8n8.x4.shared.b16 {%0,%1,%2,%3}, [%4];"
                    : "=r"(bk[2*jt2][0]), "=r"(bk[2*jt2][1]),
                      "=r"(bk[2*jt2+1][0]), "=r"(bk[2*jt2+1][1]) : "r"(addr));
            }
#pragma unroll
            for (int jt = 0; jt < 16; jt++) mma16816h(sacc[jt], aqh, bk[jt]);
#pragma unroll
            for (int jt = 0; jt < 16; jt++) mma16816h(sacc[jt], aql, bk[jt]);
        }

        // ---- bias + online softmax (rows fully in-warp) ----
        float mx0 = -1e30f, mx1 = -1e30f;
#pragma unroll
        for (int jt = 0; jt < 16; jt++) {
            int jbase = j0 + jt*8 + (lane & 3)*2;
#pragma unroll
            for (int c = 0; c < 2; c++) {
                int jg = jbase + c;
                float ukv = uks[jg];
                {
                    int dd = jg - ig0;
                    int a = dd < 0 ? -dd : dd;
                    int t = ts[a];
                    float ss = SsS[il0*33 + t];
                    float bias = SuS[il0*33 + t] + (dd > 0 ? ss : (dd < 0 ? -ss : 0.f)) + ukv;
                    float v = (sacc[jt][c] + bias) * scale;
                    sacc[jt][c] = v; mx0 = fmaxf(mx0, v);
                }
                {
                    int dd = jg - ig1;
                    int a = dd < 0 ? -dd : dd;
                    int t = ts[a];
                    float ss = SsS[(il0+8)*33 + t];
                    float bias = SuS[(il0+8)*33 + t] + (dd > 0 ? ss : (dd < 0 ? -ss : 0.f)) + ukv;
                    float v = (sacc[jt][2+c] + bias) * scale;
                    sacc[jt][2+c] = v; mx1 = fmaxf(mx1, v);
                }
            }
        }
        mx0 = fmaxf(mx0, __shfl_xor_sync(0xffffffffu, mx0, 1));
        mx0 = fmaxf(mx0, __shfl_xor_sync(0xffffffffu, mx0, 2));
        mx1 = fmaxf(mx1, __shfl_xor_sync(0xffffffffu, mx1, 1));
        mx1 = fmaxf(mx1, __shfl_xor_sync(0xffffffffu, mx1, 2));

        float mn0 = fmaxf(m0_, mx0), mn1 = fmaxf(m1_, mx1);
        float al0 = __expf(m0_ - mn0), al1 = __expf(m1_ - mn1);
        float rs0 = 0.f, rs1 = 0.f;
#pragma unroll
        for (int jt = 0; jt < 16; jt++) {
            float p0 = __expf(sacc[jt][0] - mn0);
            float p1 = __expf(sacc[jt][1] - mn0);
            float p2 = __expf(sacc[jt][2] - mn1);
            float p3 = __expf(sacc[jt][3] - mn1);
            sacc[jt][0] = p0; sacc[jt][1] = p1; sacc[jt][2] = p2; sacc[jt][3] = p3;
            rs0 += p0 + p1; rs1 += p2 + p3;
        }
        rs0 += __shfl_xor_sync(0xffffffffu, rs0, 1);
        rs0 += __shfl_xor_sync(0xffffffffu, rs0, 2);
        rs1 += __shfl_xor_sync(0xffffffffu, rs1, 1);
        rs1 += __shfl_xor_sync(0xffffffffu, rs1, 2);
        l0_ = l0_*al0 + rs0; l1_ = l1_*al1 + rs1;
        m0_ = mn0; m1_ = mn1;
#pragma unroll
        for (int d = 0; d < 8; d++) {
            oacc[d][0] *= al0; oacc[d][1] *= al0;
            oacc[d][2] *= al1; oacc[d][3] *= al1;
        }

        // ---- O += Ph @ (Vh + Vl)  (fp16-rounded P, exact V) ----
        uint32_t vHb = (uint32_t)__cvta_generic_to_shared(sVh);
        uint32_t vLb = (uint32_t)__cvta_generic_to_shared(sVl);
#pragma unroll
        for (int g = 0; g < 8; g++) {
            uint32_t aph[4];
#pragma unroll
            for (int q = 0; q < 4; q++) {
                int jt = 2*g + (q >> 1);
                int eb = (q & 1) * 2;
                __half2 hp = __floats2half2_rn(sacc[jt][eb], sacc[jt][eb+1]);
                aph[q] = *(uint32_t*)&hp;
            }

            uint32_t bv[8][2];
#pragma unroll
            for (int dt2 = 0; dt2 < 4; dt2++) {
                uint32_t addr = vHb + (uint32_t)(
                    ((dt2*16 + (lane & 7) + ((lane >> 4) << 3))*VSTR
                     + (((lane >> 3) & 1) << 3) + g*16) * 2);
                asm volatile("ldmatrix.sync.aligned.m8n8.x4.shared.b16 {%0,%1,%2,%3}, [%4];"
                    : "=r"(bv[2*dt2][0]), "=r"(bv[2*dt2][1]),
                      "=r"(bv[2*dt2+1][0]), "=r"(bv[2*dt2+1][1]) : "r"(addr));
            }
#pragma unroll
            for (int dt = 0; dt < 8; dt++) mma16816h(oacc[dt], aph, bv[dt]);
#pragma unroll
            for (int dt2 = 0; dt2 < 4; dt2++) {
                uint32_t addr = vLb + (uint32_t)(
                    ((dt2*16 + (lane & 7) + ((lane >> 4) << 3))*VSTR
                     + (((lane >> 3) & 1) << 3) + g*16) * 2);
                asm volatile("ldmatrix.sync.aligned.m8n8.x4.shared.b16 {%0,%1,%2,%3}, [%4];"
                    : "=r"(bv[2*dt2][0]), "=r"(bv[2*dt2][1]),
                      "=r"(bv[2*dt2+1][0]), "=r"(bv[2*dt2+1][1]) : "r"(addr));
            }
#pragma unroll
            for (int dt = 0; dt < 8; dt++) mma16816h(oacc[dt], aph, bv[dt]);
        }
    }

    // ---- epilogue: normalize, write fp16 hi|lo aug directly ----
    float inv0 = 1.f / l0_, inv1 = 1.f / l1_;
    int row0 = b*NL + ig0;   // global AO row for slot 0
    int colb = hh*64 + (lane & 3)*2;
#pragma unroll
    for (int dt = 0; dt < 8; dt++) {
        int col = colb + dt*8;
        float o0 = oacc[dt][0]*inv0, o1 = oacc[dt][1]*inv0;
        float o2 = oacc[dt][2]*inv1, o3 = oacc[dt][3]*inv1;
        __half h0, l0v, h1, l1v, h2, l2v, h3, l3v;
        split_hl16(o0, h0, l0v); split_hl16(o1, h1, l1v);
        split_hl16(o2, h2, l2v); split_hl16(o3, h3, l3v);
        __half* base0 = g_AOaug + (size_t)row0 * KAUG_O + col;
        __half* base1 = g_AOaug + (size_t)(row0 + 8) * KAUG_O + col;
        *(__half2*)(base0)       = __half2(h0, h1);
        *(__half2*)(base0 + 512) = __half2(l0v, l1v);
        *(__half2*)(base1)       = __half2(h2, h3);
        *(__half2*)(base1 + 512) = __half2(l2v, l3v);
    }
}

// ----------------------------------------------------------------------------
extern "C" void kernel_launch(void* const* d_in, const int* in_sizes, int n_in,
                              void* d_out, int out_size)
{
    const float* x      = (const float*)d_in[0];
    const float* Wq     = (const float*)d_in[1];
    const float* Wk     = (const float*)d_in[2];
    const float* Wv     = (const float*)d_in[3];
    const float* Wo     = (const float*)d_in[4];
    const float* bo     = (const float*)d_in[5];
    const float* u_bias = (const float*)d_in[6];
    const float* v_bias = (const float*)d_in[7];
    const float* w_pos  = (const float*)d_in[8];
    float* out = (float*)d_out;

    cudaFuncSetAttribute(attn_kernel,
                         cudaFuncAttributeMaxDynamicSharedMemorySize, ATTN_SMEM);

    pre_kernel<<<3348, 256>>>(Wq, Wk, u_bias, w_pos, v_bias, x, Wo);
    convw_uk_kernel<<<2304, 256>>>(Wq, Wk, Wv, x);

    gemm_mma<<<dim3(16, 16), 256>>>(0, nullptr, nullptr);  // QKV|QW + fused suffix/uk-free

    attn_kernel<<<dim3(8, 8, 2), 256, ATTN_SMEM>>>();

    gemm_mma<<<dim3(6, 16), 256>>>(1, bo, out);            // out proj
}

// round 16
// speedup vs baseline: 1.1801x; 1.1801x over previous
#include <cuda_runtime.h>
#include <cuda_bf16.h>
#include <cuda_fp16.h>
#include <math.h>
#include <stdint.h>

#define NB 2
#define NL 1024
#define NH 8
#define ND 64
#define NDM 768
#define HD 512        /* NH*ND */
#define QLD 2048      /* g_qkv row stride: Q|K|V|QW */
#define KAUG_X 1536   /* 2*768: [x_hi | x_lo] vs [w_hi | w_hi] */
#define KAUG_O 1024   /* 2*512 */

// ------------------------- device scratch (no allocation) --------------------
static __device__ __align__(16) __half g_Aaug [NB*NL*KAUG_X];   // x hi|lo (fp16)
static __device__ __align__(16) __half g_Waug [2048*KAUG_X];    // Wq|Wk|Wv|W2 hi|hi
static __device__ __align__(16) __half g_AOaug[NB*NL*KAUG_O];   // attn out hi|lo
static __device__ __align__(16) __half g_WOaug[NDM*KAUG_O];     // Wo hi|hi
static __device__ __align__(16) float g_W2 [HD*NDM];            // folded Wq^T@wpos
static __device__ __align__(16) float g_qkv[NB*NL*QLD];         // K|QW fp32 regions used
// fp16 attention operands, [b][h][tok][d] (Q,K) and [b][h][d][tok] (V^T)
static __device__ __align__(16) __half g_qh[NB*NH*NL*ND];
static __device__ __align__(16) __half g_ql[NB*NH*NL*ND];
static __device__ __align__(16) __half g_kh[NB*NH*NL*ND];
static __device__ __align__(16) __half g_vth[NB*NH*ND*NL];
static __device__ __align__(16) __half g_vtl[NB*NH*ND*NL];
static __device__ __align__(16) float g_uk [NB*NH*NL];
static __device__ __align__(16) float g_Su [NB*NH*NL*33];
static __device__ __align__(16) float g_Ss [NB*NH*NL*33];
static __device__ __align__(16) float g_VrU[NH*33];
static __device__ __align__(16) float g_VrS[NH*33];
static __device__ int   g_t[NL];

// ------------------------- helpers -------------------------------------------
__device__ __forceinline__ void split_hl16(float v, __half& h, __half& l) {
    h = __float2half(v);
    l = __float2half(v - __half2float(h));
}

// -------- merged pre-kernel: fold_w2 | prep | conv_x | conv_wo ---------------
// blocks [0,512): W2 fold; [512,524): prep; [524,2572): conv_x; [2572,3340): conv_wo
__global__ void pre_kernel(const float* __restrict__ Wq,
                           const float* __restrict__ w_pos,
                           const float* __restrict__ v_bias,
                           const float* __restrict__ x,
                           const float* __restrict__ Wo)
{
    const int tid = threadIdx.x;
    const int blk = blockIdx.x;

    if (blk < 512) {                       // ---- fold_w2 ----
        __shared__ float wp[64];
        int hn = blk, h = hn >> 6, n = hn & 63;
        if (tid < 64) wp[tid] = w_pos[h*4096 + tid*64 + n];
        __syncthreads();
        for (int m = tid; m < NDM; m += 256) {
            float s = 0.f;
#pragma unroll 16
            for (int d = 0; d < 64; d++)
                s += Wq[(size_t)(h*64 + d)*NDM + m] * wp[d];
            g_W2[(size_t)hn*NDM + m] = s;
        }
        return;
    }
    if (blk < 524) {                       // ---- prep ----
        int sub = blk - 512;
        if (sub < 4) {
            __shared__ float cw[32];
            if (tid < 32) {
                float pr = expf(logf((float)(NL+1) * 0.5f) / 32.f);
                cw[tid] = powf(pr, (float)(tid+1));
            }
            __syncthreads();
            int a = sub*256 + tid;
            int t = 32;
            for (int f = 0; f < 32; f++)
                if ((float)a <= cw[f]) { t = f; break; }
            g_t[a] = t;
            return;
        }
        int hh = sub - 4;
        __shared__ float vws[64];
        if (tid < 64) {
            int n = tid;
            float s = 0.f;
            for (int d = 0; d < 64; d++)
                s += v_bias[hh*64 + d] * w_pos[hh*4096 + d*64 + n];
            vws[n] = s;
        }
        __syncthreads();
        if (tid < 2) {
            int half = tid;
            float* dst = (half ? g_VrS : g_VrU) + hh*33;
            const float* src = vws + half*32;
            float run = 0.f;
            dst[32] = 0.f;
            for (int f = 31; f >= 0; f--) { run += src[f]; dst[f] = run; }
        }
        return;
    }
    if (blk < 2572) {                      // ---- conv_x ----
        int row = blk - 524;
        const float* src = x + (size_t)row * NDM;
        __half* dst = g_Aaug + (size_t)row * KAUG_X;
        for (int c = tid; c < NDM; c += 256) {
            __half h, l; split_hl16(src[c], h, l);
            dst[c] = h; dst[NDM + c] = l;
        }
        return;
    }
    {                                      // ---- conv_wo ----
        int r = blk - 2572;
        const float* src = Wo + (size_t)r * HD;
        __half* dst = g_WOaug + (size_t)r * KAUG_O;
        for (int c = tid; c < HD; c += 256) {
            __half h = __float2half(src[c]);
            dst[c] = h; dst[HD + c] = h;
        }
    }
}

__global__ void conv_w_kernel(const float* __restrict__ Wq,
                              const float* __restrict__ Wk,
                              const float* __restrict__ Wv) {  // grid 2048
    int r = blockIdx.x;
    const float* src;
    if (r < 512)        src = Wq + (size_t)r * NDM;
    else if (r < 1024)  src = Wk + (size_t)(r-512) * NDM;
    else if (r < 1536)  src = Wv + (size_t)(r-1024) * NDM;
    else                src = g_W2 + (size_t)(r-1536) * NDM;
    __half* dst = g_Waug + (size_t)r * KAUG_X;
    for (int c = threadIdx.x; c < NDM; c += 256) {
        __half h = __float2half(src[c]);
        dst[c] = h; dst[NDM + c] = h;
    }
}

// ------------------------- mma.sync fp16 GEMM: C = A @ Bw^T ------------------
#define BM 128
#define BN 128
#define BK 32
#define GSTR 40

__device__ __forceinline__ void mma16816h(float* c, const uint32_t* a, const uint32_t* b) {
    asm volatile(
        "mma.sync.aligned.m16n8k16.row.col.f32.f16.f16.f32 "
        "{%0,%1,%2,%3}, {%4,%5,%6,%7}, {%8,%9}, {%0,%1,%2,%3};"
        : "+f"(c[0]), "+f"(c[1]), "+f"(c[2]), "+f"(c[3])
        : "r"(a[0]), "r"(a[1]), "r"(a[2]), "r"(a[3]), "r"(b[0]), "r"(b[1]));
}

__global__ __launch_bounds__(256, 1)
void gemm_mma(int which, const float* __restrict__ bias, float* __restrict__ Cout)
{
    __shared__ __half sA[2][BM*GSTR];
    __shared__ __half sB[2][BN*GSTR];

    const int tid = threadIdx.x;
    const int wid = tid >> 5, lane = tid & 31;
    const int wm = wid >> 2, wn = wid & 3;
    const int m0 = blockIdx.y * BM, n0 = blockIdx.x * BN;

    const __half *A, *Bw;
    float* C; int Kaug, Ntot;
    if (which == 0) { A = g_Aaug;  Bw = g_Waug;  C = g_qkv; Kaug = KAUG_X; Ntot = QLD; }
    else            { A = g_AOaug; Bw = g_WOaug; C = Cout;  Kaug = KAUG_O; Ntot = NDM; }
    const int nk = Kaug / BK;

    const int ldrow = tid >> 2, ldg = tid & 3;

    auto prefetch = [&](int c) {
        int p = c & 1;
        {
            const __half* Ab = A + (size_t)(m0 + ldrow) * Kaug + c*BK + ldg*8;
#pragma unroll
            for (int s = 0; s < 2; s++) {
                uint32_t dst = (uint32_t)__cvta_generic_to_shared(
                    &sA[p][(ldrow + s*64)*GSTR + ldg*8]);
                const void* src = Ab + (size_t)(s*64) * Kaug;
                asm volatile("cp.async.cg.shared.global [%0], [%1], 16;" :: "r"(dst), "l"(src));
            }
        }
        {
            const __half* Bb = Bw + (size_t)(n0 + ldrow) * Kaug + c*BK + ldg*8;
#pragma unroll
            for (int s = 0; s < 2; s++) {
                uint32_t dst = (uint32_t)__cvta_generic_to_shared(
                    &sB[p][(ldrow + s*64)*GSTR + ldg*8]);
                const void* src = Bb + (size_t)(s*64) * Kaug;
                asm volatile("cp.async.cg.shared.global [%0], [%1], 16;" :: "r"(dst), "l"(src));
            }
        }
        asm volatile("cp.async.commit_group;" ::: "memory");
    };

    float acc[4][4][4];
#pragma unroll
    for (int i = 0; i < 4; i++)
#pragma unroll
        for (int j = 0; j < 4; j++)
#pragma unroll
            for (int r = 0; r < 4; r++) acc[i][j][r] = 0.f;

    prefetch(0);

    for (int c = 0; c < nk; c++) {
        int p = c & 1;
        if (c + 1 < nk) {
            prefetch(c + 1);
            asm volatile("cp.async.wait_group 1;" ::: "memory");
        } else {
            asm volatile("cp.async.wait_group 0;" ::: "memory");
        }
        __syncthreads();

        uint32_t aB = (uint32_t)__cvta_generic_to_shared(&sA[p][0]);
        uint32_t bB = (uint32_t)__cvta_generic_to_shared(&sB[p][0]);

#pragma unroll
        for (int ks = 0; ks < 2; ks++) {
            uint32_t a[4][4];
#pragma unroll
            for (int i = 0; i < 4; i++) {
                uint32_t addr = aB + (uint32_t)(
                    ((wm*64 + i*16 + (lane & 15))*GSTR + ((lane >> 4)*8) + ks*16) * 2);
                asm volatile("ldmatrix.sync.aligned.m8n8.x4.shared.b16 {%0,%1,%2,%3}, [%4];"
                    : "=r"(a[i][0]), "=r"(a[i][1]), "=r"(a[i][2]), "=r"(a[i][3]) : "r"(addr));
            }
            uint32_t b[4][2];
#pragma unroll
            for (int jp = 0; jp < 2; jp++) {
                uint32_t addr = bB + (uint32_t)(
                    ((wn*32 + jp*16 + (lane & 7) + ((lane >> 4) << 3))*GSTR
                     + (((lane >> 3) & 1) << 3) + ks*16) * 2);
                asm volatile("ldmatrix.sync.aligned.m8n8.x4.shared.b16 {%0,%1,%2,%3}, [%4];"
                    : "=r"(b[2*jp][0]), "=r"(b[2*jp][1]),
                      "=r"(b[2*jp+1][0]), "=r"(b[2*jp+1][1]) : "r"(addr));
            }
#pragma unroll
            for (int i = 0; i < 4; i++)
#pragma unroll
                for (int j = 0; j < 4; j++)
                    mma16816h(acc[i][j], a[i], b[j]);
        }
        __syncthreads();
    }

    // epilogue
    if (which == 1) {
#pragma unroll
        for (int i = 0; i < 4; i++) {
            int r0 = m0 + wm*64 + i*16 + (lane >> 2);
#pragma unroll
            for (int j = 0; j < 4; j++) {
                int col = n0 + wn*32 + j*8 + (lane & 3)*2;
                float b0 = bias[col], b1 = bias[col+1];
                *(float2*)(C + (size_t)r0 * Ntot + col) =
                    make_float2(acc[i][j][0] + b0, acc[i][j][1] + b1);
                *(float2*)(C + (size_t)(r0 + 8) * Ntot + col) =
                    make_float2(acc[i][j][2] + b0, acc[i][j][3] + b1);
            }
        }
        return;
    }

    // which == 0: scatter into fp32 (K,QW regions) + fp16 attention operands
    auto emit = [&](int row, int col, float v0, float v1) {
        int reg = col >> 9;
        int bb = row >> 10, tok = row & 1023;
        int h = (col >> 6) & 7, d = col & 63;
        if (reg == 1 || reg == 3)
            *(float2*)(g_qkv + (size_t)row*QLD + col) = make_float2(v0, v1);
        if (reg == 3) return;
        __half h0, l0, h1, l1;
        split_hl16(v0, h0, l0); split_hl16(v1, h1, l1);
        if (reg == 2) {
            size_t vk = ((size_t)((bb*8+h)*64 + d))*1024 + tok;
            g_vth[vk] = h0; g_vtl[vk] = l0;
            g_vth[vk + 1024] = h1; g_vtl[vk + 1024] = l1;
            return;
        }
        size_t qk = ((size_t)((bb*8+h)*1024 + tok))*64 + d;
        if (reg == 0) {
            *(__half2*)(g_qh + qk) = __half2(h0, h1);
            *(__half2*)(g_ql + qk) = __half2(l0, l1);
        } else {
            *(__half2*)(g_kh + qk) = __half2(h0, h1);
        }
    };
#pragma unroll
    for (int i = 0; i < 4; i++) {
        int r0 = m0 + wm*64 + i*16 + (lane >> 2);
#pragma unroll
        for (int j = 0; j < 4; j++) {
            int col = n0 + wn*32 + j*8 + (lane & 3)*2;
            emit(r0,     col, acc[i][j][0], acc[i][j][1]);
            emit(r0 + 8, col, acc[i][j][2], acc[i][j][3]);
        }
    }
}

// -------- merged: suffix sums of qw rows (+vr) AND uk dot products -----------
__global__ __launch_bounds__(256)
void uksuf_kernel(const float* __restrict__ u_bias)
{
    if (blockIdx.x < 4096) {
        int gw = blockIdx.x*8 + (threadIdx.x >> 5);
        int lane = threadIdx.x & 31;
        int half = gw & 1;
        int pair = gw >> 1;
        int h = pair & 7;
        int row = pair >> 3;
        int b = row >> 10, i = row & 1023;

        float v = g_qkv[(size_t)row*QLD + 1536 + h*64 + half*32 + lane];
#pragma unroll
        for (int o = 1; o < 32; o <<= 1) {
            float t = __shfl_down_sync(0xffffffffu, v, o);
            if (lane + o < 32) v += t;
        }
        const float* vr = (half ? g_VrS : g_VrU) + h*33;
        float* dst = (half ? g_Ss : g_Su) + (size_t)((b*NH + h)*NL + i)*33;
        dst[lane] = v + vr[lane];
        if (lane == 0) dst[32] = vr[32];
        return;
    }
    int idx = (blockIdx.x - 4096)*256 + threadIdx.x;   // 0..16383
    int bh = idx >> 10, j = idx & 1023;
    int b = bh >> 3, hh = bh & 7;
    const float* kr = g_qkv + (size_t)(b*NL + j)*QLD + 512 + hh*ND;
    const float* ub = u_bias + hh*ND;
    float s = 0.f;
#pragma unroll
    for (int d = 0; d < ND; d += 4) {
        float4 kv = *(const float4*)(kr + d);
        float4 uv = *(const float4*)(ub + d);
        s += kv.x*uv.x + kv.y*uv.y + kv.z*uv.z + kv.w*uv.w;
    }
    g_uk[idx] = s;
}

// ---------------- flash attention, fp16 HMMA, cp.async K/V pipeline ----------
#define QSTR 72    /* Q/K smem row stride (fp16): 144B, 144%128=16 -> conflict-free */
#define VSTR 136   /* V^T smem row stride: 272B, %128=16 */
#define KSTG (128*QSTR*2)   /* 18432 B per K stage */
#define VSTG (64*VSTR*2)    /* 17408 B per V stage */
#define AOFF_QH 0
#define AOFF_QL (AOFF_QH + 128*QSTR*2)
#define AOFF_KH (AOFF_QL + 128*QSTR*2)
#define AOFF_VH (AOFF_KH + 2*KSTG)
#define AOFF_VL (AOFF_VH + 2*VSTG)
#define AOFF_SU (AOFF_VL + 2*VSTG)
#define AOFF_SS (AOFF_SU + 128*33*4)
#define AOFF_UK (AOFF_SS + 128*33*4)
#define AOFF_TS (AOFF_UK + 1024*4)
#define ATTN_SMEM (AOFF_TS + 1024*4)

__global__ __launch_bounds__(256, 1)
void attn_kernel()
{
    extern __shared__ char smc[];
    __half* sQh = (__half*)(smc + AOFF_QH);
    __half* sQl = (__half*)(smc + AOFF_QL);
    __half* sKh = (__half*)(smc + AOFF_KH);
    __half* sVh = (__half*)(smc + AOFF_VH);
    __half* sVl = (__half*)(smc + AOFF_VL);
    float* SuS = (float*)(smc + AOFF_SU);
    float* SsS = (float*)(smc + AOFF_SS);
    float* uks = (float*)(smc + AOFF_UK);
    int*   ts  = (int*)(smc + AOFF_TS);

    const int tid = threadIdx.x;
    const int wid = tid >> 5, lane = tid & 31;
    const int it = blockIdx.x, hh = blockIdx.y, b = blockIdx.z;
    const int i0 = it * 128;
    const int bh = b*NH + hh;
    const float scale = 0.125f;

    const size_t qkbase = (size_t)(bh*NL) * ND;      // Q/K [tok][d]
    const size_t vtbase = (size_t)(bh*ND) * NL;      // V^T [d][tok]

    // async K/V stage loader: 12 x 16B cp.async per thread per chunk
    auto load_kv = [&](int jc) {
        int p = jc & 1;
        int j0 = jc * 128;
#pragma unroll
        for (int s = 0; s < 4; s++) {              // K: 1024 chunks / 256 thr
            int idx = tid + 256*s;
            int row = idx >> 3, g = idx & 7;
            uint32_t dst = (uint32_t)__cvta_generic_to_shared(
                sKh + p*(KSTG/2) + row*QSTR + g*8);
            const void* src = g_kh + qkbase + (size_t)(j0 + row)*ND + g*8;
            asm volatile("cp.async.cg.shared.global [%0], [%1], 16;" :: "r"(dst), "l"(src));
        }
#pragma unroll
        for (int s = 0; s < 4; s++) {              // VH+VL: 1024 chunks each
            int idx = tid + 256*s;
            int d = idx >> 4, g = idx & 15;
            size_t src = vtbase + (size_t)d*NL + j0 + g*8;
            uint32_t dsth = (uint32_t)__cvta_generic_to_shared(
                sVh + p*(VSTG/2) + d*VSTR + g*8);
            asm volatile("cp.async.cg.shared.global [%0], [%1], 16;" :: "r"(dsth), "l"(g_vth + src));
            uint32_t dstl = (uint32_t)__cvta_generic_to_shared(
                sVl + p*(VSTG/2) + d*VSTR + g*8);
            asm volatile("cp.async.cg.shared.global [%0], [%1], 16;" :: "r"(dstl), "l"(g_vtl + src));
        }
        asm volatile("cp.async.commit_group;" ::: "memory");
    };

    load_kv(0);   // stage 0 in flight while we do the prologue

    // prologue: Q tiles + tables
    for (int idx = tid; idx < 1024; idx += 256) {    // 128 rows x 8 chunks(16B)
        int row = idx >> 3, g = idx & 7;
        size_t src = qkbase + (size_t)(i0 + row)*ND + g*8;
        *(uint4*)(sQh + row*QSTR + g*8) = *(const uint4*)(g_qh + src);
        *(uint4*)(sQl + row*QSTR + g*8) = *(const uint4*)(g_ql + src);
    }
    for (int idx = tid; idx < 128*33; idx += 256) {
        SuS[idx] = g_Su[(size_t)(bh*NL + i0)*33 + idx];
        SsS[idx] = g_Ss[(size_t)(bh*NL + i0)*33 + idx];
    }
    for (int idx = tid; idx < NL; idx += 256) {
        uks[idx] = g_uk[bh*NL + idx];
        ts[idx]  = g_t[idx];
    }

    const int il0 = wid*16 + (lane >> 2);
    const int ig0 = i0 + il0, ig1 = ig0 + 8;

    float m0_ = -1e30f, m1_ = -1e30f, l0_ = 0.f, l1_ = 0.f;
    float oacc[8][4];
#pragma unroll
    for (int d = 0; d < 8; d++)
#pragma unroll
        for (int e = 0; e < 4; e++) oacc[d][e] = 0.f;

    for (int jc = 0; jc < 8; jc++) {
        const int j0 = jc * 128;
        const int p = jc & 1;
        __syncthreads();   // all warps done reading the buffer we overwrite next
        if (jc + 1 < 8) {
            load_kv(jc + 1);
            asm volatile("cp.async.wait_group 1;" ::: "memory");
        } else {
            asm volatile("cp.async.wait_group 0;" ::: "memory");
        }
        __syncthreads();

        // ---- S = (Qh + Ql) @ Kh^T  (exact Q, fp16-rounded K) ----
        float sacc[16][4];
#pragma unroll
        for (int jt = 0; jt < 16; jt++)
#pragma unroll
            for (int e = 0; e < 4; e++) sacc[jt][e] = 0.f;

        uint32_t aQbase = (uint32_t)__cvta_generic_to_shared(sQh);
        uint32_t aQlb   = (uint32_t)__cvta_generic_to_shared(sQl);
        uint32_t aKbase = (uint32_t)__cvta_generic_to_shared(sKh + p*(KSTG/2));

#pragma unroll
        for (int ks = 0; ks < 4; ks++) {
            uint32_t aqh[4], aql[4];
            {
                uint32_t addr = aQbase + (uint32_t)(
                    ((wid*16 + (lane & 15))*QSTR + (lane >> 4)*8 + ks*16) * 2);
                asm volatile("ldmatrix.sync.aligned.m8n8.x4.shared.b16 {%0,%1,%2,%3}, [%4];"
                    : "=r"(aqh[0]), "=r"(aqh[1]), "=r"(aqh[2]), "=r"(aqh[3]) : "r"(addr));
                addr = aQlb + (uint32_t)(
                    ((wid*16 + (lane & 15))*QSTR + (lane >> 4)*8 + ks*16) * 2);
                asm volatile("ldmatrix.sync.aligned.m8n8.x4.shared.b16 {%0,%1,%2,%3}, [%4];"
                    : "=r"(aql[0]), "=r"(aql[1]), "=r"(aql[2]), "=r"(aql[3]) : "r"(addr));
            }
            uint32_t bk[16][2];
#pragma unroll
            for (int jt2 = 0; jt2 < 8; jt2++) {
                uint32_t addr = aKbase + (uint32_t)(
                    ((jt2*16 + (lane & 7) + ((lane >> 4) << 3))*QSTR
                     + (((lane >> 3) & 1) << 3) + ks*16) * 2);
                asm volatile("ldmatrix.sync.aligned.m8n8.x4.shared.b16 {%0,%1,%2,%3}, [%4];"
                    : "=r"(bk[2*jt2][0]), "=r"(bk[2*jt2][1]),
                      "=r"(bk[2*jt2+1][0]), "=r"(bk[2*jt2+1][1]) : "r"(addr));
            }
#pragma unroll
            for (int jt = 0; jt < 16; jt++) mma16816h(sacc[jt], aqh, bk[jt]);
#pragma unroll
            for (int jt = 0; jt < 16; jt++) mma16816h(sacc[jt], aql, bk[jt]);
        }

        // ---- bias + online softmax (rows fully in-warp) ----
        float mx0 = -1e30f, mx1 = -1e30f;
#pragma unroll
        for (int jt = 0; jt < 16; jt++) {
            int jbase = j0 + jt*8 + (lane & 3)*2;
#pragma unroll
            for (int c = 0; c < 2; c++) {
                int jg = jbase + c;
                float ukv = uks[jg];
                {
                    int dd = jg - ig0;
                    int a = dd < 0 ? -dd : dd;
                    int t = ts[a];
                    float ss = SsS[il0*33 + t];
                    float bias = SuS[il0*33 + t] + (dd > 0 ? ss : (dd < 0 ? -ss : 0.f)) + ukv;
                    float v = (sacc[jt][c] + bias) * scale;
                    sacc[jt][c] = v; mx0 = fmaxf(mx0, v);
                }
                {
                    int dd = jg - ig1;
                    int a = dd < 0 ? -dd : dd;
                    int t = ts[a];
                    float ss = SsS[(il0+8)*33 + t];
                    float bias = SuS[(il0+8)*33 + t] + (dd > 0 ? ss : (dd < 0 ? -ss : 0.f)) + ukv;
                    float v = (sacc[jt][2+c] + bias) * scale;
                    sacc[jt][2+c] = v; mx1 = fmaxf(mx1, v);
                }
            }
        }
        mx0 = fmaxf(mx0, __shfl_xor_sync(0xffffffffu, mx0, 1));
        mx0 = fmaxf(mx0, __shfl_xor_sync(0xffffffffu, mx0, 2));
        mx1 = fmaxf(mx1, __shfl_xor_sync(0xffffffffu, mx1, 1));
        mx1 = fmaxf(mx1, __shfl_xor_sync(0xffffffffu, mx1, 2));

        float mn0 = fmaxf(m0_, mx0), mn1 = fmaxf(m1_, mx1);
        float al0 = __expf(m0_ - mn0), al1 = __expf(m1_ - mn1);
        float rs0 = 0.f, rs1 = 0.f;
#pragma unroll
        for (int jt = 0; jt < 16; jt++) {
            float p0 = __expf(sacc[jt][0] - mn0);
            float p1 = __expf(sacc[jt][1] - mn0);
            float p2 = __expf(sacc[jt][2] - mn1);
            float p3 = __expf(sacc[jt][3] - mn1);
            sacc[jt][0] = p0; sacc[jt][1] = p1; sacc[jt][2] = p2; sacc[jt][3] = p3;
            rs0 += p0 + p1; rs1 += p2 + p3;
        }
        rs0 += __shfl_xor_sync(0xffffffffu, rs0, 1);
        rs0 += __shfl_xor_sync(0xffffffffu, rs0, 2);
        rs1 += __shfl_xor_sync(0xffffffffu, rs1, 1);
        rs1 += __shfl_xor_sync(0xffffffffu, rs1, 2);
        l0_ = l0_*al0 + rs0; l1_ = l1_*al1 + rs1;
        m0_ = mn0; m1_ = mn1;
#pragma unroll
        for (int d = 0; d < 8; d++) {
            oacc[d][0] *= al0; oacc[d][1] *= al0;
            oacc[d][2] *= al1; oacc[d][3] *= al1;
        }

        // ---- O += Ph @ (Vh + Vl)  (fp16-rounded P, exact V) ----
        uint32_t vHb = (uint32_t)__cvta_generic_to_shared(sVh + p*(VSTG/2));
        uint32_t vLb = (uint32_t)__cvta_generic_to_shared(sVl + p*(VSTG/2));
#pragma unroll
        for (int g = 0; g < 8; g++) {
            uint32_t aph[4];
#pragma unroll
            for (int q = 0; q < 4; q++) {
                int jt = 2*g + (q >> 1);
                int eb = (q & 1) * 2;
                __half2 hp = __floats2half2_rn(sacc[jt][eb], sacc[jt][eb+1]);
                aph[q] = *(uint32_t*)&hp;
            }

            uint32_t bv[8][2];
#pragma unroll
            for (int dt2 = 0; dt2 < 4; dt2++) {
                uint32_t addr = vHb + (uint32_t)(
                    ((dt2*16 + (lane & 7) + ((lane >> 4) << 3))*VSTR
                     + (((lane >> 3) & 1) << 3) + g*16) * 2);
                asm volatile("ldmatrix.sync.aligned.m8n8.x4.shared.b16 {%0,%1,%2,%3}, [%4];"
                    : "=r"(bv[2*dt2][0]), "=r"(bv[2*dt2][1]),
                      "=r"(bv[2*dt2+1][0]), "=r"(bv[2*dt2+1][1]) : "r"(addr));
            }
#pragma unroll
            for (int dt = 0; dt < 8; dt++) mma16816h(oacc[dt], aph, bv[dt]);
#pragma unroll
            for (int dt2 = 0; dt2 < 4; dt2++) {
                uint32_t addr = vLb + (uint32_t)(
                    ((dt2*16 + (lane & 7) + ((lane >> 4) << 3))*VSTR
                     + (((lane >> 3) & 1) << 3) + g*16) * 2);
                asm volatile("ldmatrix.sync.aligned.m8n8.x4.shared.b16 {%0,%1,%2,%3}, [%4];"
                    : "=r"(bv[2*dt2][0]), "=r"(bv[2*dt2][1]),
                      "=r"(bv[2*dt2+1][0]), "=r"(bv[2*dt2+1][1]) : "r"(addr));
            }
#pragma unroll
            for (int dt = 0; dt < 8; dt++) mma16816h(oacc[dt], aph, bv[dt]);
        }
    }

    // ---- epilogue: normalize, write fp16 hi|lo aug directly ----
    float inv0 = 1.f / l0_, inv1 = 1.f / l1_;
    int row0 = b*NL + ig0;   // global AO row for slot 0
    int colb = hh*64 + (lane & 3)*2;
#pragma unroll
    for (int dt = 0; dt < 8; dt++) {
        int col = colb + dt*8;
        float o0 = oacc[dt][0]*inv0, o1 = oacc[dt][1]*inv0;
        float o2 = oacc[dt][2]*inv1, o3 = oacc[dt][3]*inv1;
        __half h0, l0v, h1, l1v, h2, l2v, h3, l3v;
        split_hl16(o0, h0, l0v); split_hl16(o1, h1, l1v);
        split_hl16(o2, h2, l2v); split_hl16(o3, h3, l3v);
        __half* base0 = g_AOaug + (size_t)row0 * KAUG_O + col;
        __half* base1 = g_AOaug + (size_t)(row0 + 8) * KAUG_O + col;
        *(__half2*)(base0)       = __half2(h0, h1);
        *(__half2*)(base0 + 512) = __half2(l0v, l1v);
        *(__half2*)(base1)       = __half2(h2, h3);
        *(__half2*)(base1 + 512) = __half2(l2v, l3v);
    }
}

// ----------------------------------------------------------------------------
extern "C" void kernel_launch(void* const* d_in, const int* in_sizes, int n_in,
                              void* d_out, int out_size)
{
    const float* x      = (const float*)d_in[0];
    const float* Wq     = (const float*)d_in[1];
    const float* Wk     = (const float*)d_in[2];
    const float* Wv     = (const float*)d_in[3];
    const float* Wo     = (const float*)d_in[4];
    const float* bo     = (const float*)d_in[5];
    const float* u_bias = (const float*)d_in[6];
    const float* v_bias = (const float*)d_in[7];
    const float* w_pos  = (const float*)d_in[8];
    float* out = (float*)d_out;

    cudaFuncSetAttribute(attn_kernel,
                         cudaFuncAttributeMaxDynamicSharedMemorySize, ATTN_SMEM);

    pre_kernel<<<3340, 256>>>(Wq, w_pos, v_bias, x, Wo);   // fold|prep|conv_x|conv_wo
    conv_w_kernel<<<2048, 256>>>(Wq, Wk, Wv);

    gemm_mma<<<dim3(16, 16), 256>>>(0, nullptr, nullptr);  // fused QKV|QW

    uksuf_kernel<<<4160, 256>>>(u_bias);
    attn_kernel<<<dim3(8, 8, 2), 256, ATTN_SMEM>>>();

    gemm_mma<<<dim3(6, 16), 256>>>(1, bo, out);            // out proj
}